// round 7
// baseline (speedup 1.0000x reference)
#include <cuda_runtime.h>

#define SPATIAL  3136
#define NBW      128
#define SCALE2   0.35355339059327373f   // 2/sqrt(32)

// phase1: 8-row chunks = 224 positions, 56 16B-lines per channel row
#define ROWB      896                  // 56 lines * 16B
#define TEN       (32 * ROWB)          // 28672 B per tensor
#define ACHUNK    (2 * TEN)            // 57344 B (K+V)
#define P1_SMEM   (2 * ACHUNK)         // 114688 B ring-2

__device__ float g_Pp[NBW * 2 * 1024];   // unscaled partial K^T V (2 slices)

typedef unsigned long long ull;

__device__ __forceinline__ void fma2(ull& d, ull a, ull b) {
    asm("fma.rn.f32x2 %0, %1, %2, %0;" : "+l"(d) : "l"(a), "l"(b));
}
__device__ __forceinline__ ull rep2(float x) {
    ull r; asm("mov.b64 %0, {%1, %1};" : "=l"(r) : "f"(x)); return r;
}
__device__ __forceinline__ float lo32(ull x) { return __uint_as_float((unsigned)x); }
__device__ __forceinline__ float hi32(ull x) { return __uint_as_float((unsigned)(x >> 32)); }
__device__ __forceinline__ void cp16(unsigned dst, const void* src) {
    asm volatile("cp.async.cg.shared.global [%0], [%1], 16;" :: "r"(dst), "l"(src));
}

// ---------------------------------------------------------------------------
// Phase 1: partial P = K^T V.  grid (128 bw, 2 slices), 256 thr, 2 blk/SM.
// 8-row chunks (slice0: 4 chunks, slice1: 3), ring-2 cp.async.
// Thread tile 8c1 x 4c2; warp owns one 16B line (2 pos-pairs) per u-step.
// ---------------------------------------------------------------------------
__global__ __launch_bounds__(256, 2)
void phase1(const float* __restrict__ K, const float* __restrict__ V) {
    extern __shared__ __align__(16) char sm[];
    const unsigned sm32 = (unsigned)__cvta_generic_to_shared(sm);

    const int tid  = threadIdx.x;
    const int bw   = blockIdx.x;
    const int sl   = blockIdx.y;
    const int c0   = sl ? 4 : 0;
    const int nch  = sl ? 3 : 4;

    const int win  = bw & 1;
    const int head = (bw >> 1) & 7;
    const int tb   = bw >> 4;
    const int base = (tb * 256 + head * 32) * SPATIAL + win * 28;

    const int wid  = tid >> 5;
    const int lane = tid & 31;
    const int ti   = lane & 3;           // 8 c1 channels
    const int tj   = lane >> 2;          // 4 c2 channels

    auto stage = [&](int ch, int buf) {
        const unsigned bufb = sm32 + buf * ACHUNK;
        const int gofs = base + ch * 448;
        #pragma unroll
        for (int it = 0; it < 14; it++) {
            int idx = it * 256 + tid;               // 0..3583
            int tensor = (idx >= 1792) ? 1 : 0;
            int rem = idx - tensor * 1792;
            int c = rem / 56;
            int g = rem - c * 56;                   // line 0..55
            int r = g / 7;
            int w4 = g - r * 7;
            const float* src = (tensor ? V : K) + gofs + c * SPATIAL + r * 56 + w4 * 4;
            int chs = g ^ ((c >> 2) & 7);
            cp16(bufb + tensor * TEN + c * ROWB + chs * 16, src);
        }
        asm volatile("cp.async.commit_group;");
    };

    ull acc[8][4];
    #pragma unroll
    for (int i = 0; i < 8; i++)
        #pragma unroll
        for (int j = 0; j < 4; j++) acc[i][j] = 0ull;

    stage(c0, 0);

    const int keyA = (ti * 2) & 7;
    const int keyB = (ti * 2 + 1) & 7;

    for (int i = 0; i < nch; i++) {
        if (i + 1 < nch) {
            stage(c0 + i + 1, (i + 1) & 1);
            asm volatile("cp.async.wait_group 1;");
        } else {
            asm volatile("cp.async.wait_group 0;");
        }
        __syncthreads();

        const char* kB = sm + (i & 1) * ACHUNK;
        const char* vB = kB + TEN;

        #pragma unroll
        for (int u = 0; u < 7; u++) {
            const int line = wid + u * 8;           // 0..55
            ulonglong2 vv[4];
            #pragma unroll
            for (int j = 0; j < 4; j++)
                vv[j] = *(const ulonglong2*)(vB + (tj * 4 + j) * ROWB
                          + ((line ^ tj) << 4));
            {
                ulonglong2 kk[4];
                #pragma unroll
                for (int i2 = 0; i2 < 4; i2++)
                    kk[i2] = *(const ulonglong2*)(kB + (ti * 8 + i2) * ROWB
                              + ((line ^ keyA) << 4));
                #pragma unroll
                for (int i2 = 0; i2 < 4; i2++)
                    #pragma unroll
                    for (int j = 0; j < 4; j++) {
                        fma2(acc[i2][j], kk[i2].x, vv[j].x);
                        fma2(acc[i2][j], kk[i2].y, vv[j].y);
                    }
            }
            {
                ulonglong2 kk[4];
                #pragma unroll
                for (int i2 = 0; i2 < 4; i2++)
                    kk[i2] = *(const ulonglong2*)(kB + (ti * 8 + 4 + i2) * ROWB
                              + ((line ^ keyB) << 4));
                #pragma unroll
                for (int i2 = 0; i2 < 4; i2++)
                    #pragma unroll
                    for (int j = 0; j < 4; j++) {
                        fma2(acc[4 + i2][j], kk[i2].x, vv[j].x);
                        fma2(acc[4 + i2][j], kk[i2].y, vv[j].y);
                    }
            }
        }
        __syncthreads();
    }

    // reduce 8 pos-warps via smem (buffers free now)
    float* red = (float*)sm;
    #pragma unroll
    for (int i2 = 0; i2 < 8; i2++)
        #pragma unroll
        for (int j = 0; j < 4; j++)
            red[wid * 1024 + (ti * 8 + i2) * 32 + tj * 4 + j] =
                lo32(acc[i2][j]) + hi32(acc[i2][j]);
    __syncthreads();

    float* gp = g_Pp + (bw * 2 + sl) * 1024;
    #pragma unroll
    for (int t = 0; t < 4; t++) {
        const int o = tid + t * 256;
        float s = red[o];
        #pragma unroll
        for (int w = 1; w < 8; w++) s += red[w * 1024 + o];
        gp[o] = s;
    }
}

// ---------------------------------------------------------------------------
// Phase 2: out = Q * P.  grid (128 bw, 7 chunks of 8 rows), 224 threads.
// Thread tile: 4 positions x 8 c2; psd pre-duplicated (zero MOVs in loop).
// 4 blocks/SM target -> 28 warps/SM.
// ---------------------------------------------------------------------------
__global__ __launch_bounds__(224, 4)
void phase2(const float* __restrict__ Q, float* __restrict__ O) {
    __shared__ __align__(16) float qs[32 * 224];
    __shared__ __align__(16) float psd[2048];      // [c1][c2 dup-pair]

    const int tid = threadIdx.x;
    const int bw  = blockIdx.x;
    const int ck  = blockIdx.y;
    const int win  = bw & 1;
    const int head = (bw >> 1) & 7;
    const int tb   = bw >> 4;
    const int base = (tb * 256 + head * 32) * SPATIAL + win * 28 + ck * 448;

    // stage Q tile via cp.async: 1792 lines / 224 thr = 8 each
    const unsigned qsa = (unsigned)__cvta_generic_to_shared(qs);
    #pragma unroll
    for (int it = 0; it < 8; it++) {
        int idx = it * 224 + tid;
        int c = idx / 56;
        int g = idx - c * 56;
        int r = g / 7;
        int w4 = g - r * 7;
        cp16(qsa + (c * 224 + g * 4) * 4,
             Q + base + c * SPATIAL + r * 56 + w4 * 4);
    }
    asm volatile("cp.async.commit_group;");

    // build duplicated P while Q streams in
    const float* p0 = g_Pp + bw * 2048;
    for (int w = tid; w < 1024; w += 224) {
        float s = (p0[w] + p0[1024 + w]) * SCALE2;
        const int c1 = w >> 5, c2 = w & 31;
        *(ull*)&psd[c1 * 64 + c2 * 2] = rep2(s);
    }

    asm volatile("cp.async.wait_group 0;");
    __syncthreads();

    const int c2g  = tid & 3;            // 8 c2 each
    const int posg = tid >> 2;            // 0..55, all active
    const int pbase = posg * 4;

    ull a[2][8];
    #pragma unroll
    for (int p = 0; p < 2; p++)
        #pragma unroll
        for (int j = 0; j < 8; j++) a[p][j] = 0ull;

    #pragma unroll
    for (int c1 = 0; c1 < 32; c1++) {
        ulonglong2 q2 = *(const ulonglong2*)&qs[c1 * 224 + pbase];
        ulonglong2 pd0 = *(const ulonglong2*)&psd[c1 * 64 + c2g * 16];
        ulonglong2 pd1 = *(const ulonglong2*)&psd[c1 * 64 + c2g * 16 + 4];
        ulonglong2 pd2 = *(const ulonglong2*)&psd[c1 * 64 + c2g * 16 + 8];
        ulonglong2 pd3 = *(const ulonglong2*)&psd[c1 * 64 + c2g * 16 + 12];
        fma2(a[0][0], q2.x, pd0.x); fma2(a[1][0], q2.y, pd0.x);
        fma2(a[0][1], q2.x, pd0.y); fma2(a[1][1], q2.y, pd0.y);
        fma2(a[0][2], q2.x, pd1.x); fma2(a[1][2], q2.y, pd1.x);
        fma2(a[0][3], q2.x, pd1.y); fma2(a[1][3], q2.y, pd1.y);
        fma2(a[0][4], q2.x, pd2.x); fma2(a[1][4], q2.y, pd2.x);
        fma2(a[0][5], q2.x, pd2.y); fma2(a[1][5], q2.y, pd2.y);
        fma2(a[0][6], q2.x, pd3.x); fma2(a[1][6], q2.y, pd3.x);
        fma2(a[0][7], q2.x, pd3.y); fma2(a[1][7], q2.y, pd3.y);
    }

    const int rr = pbase / 28;
    const int ww = pbase - rr * 28;
    float* ob = O + base + rr * 56 + ww;
    #pragma unroll
    for (int j = 0; j < 8; j++) {
        const int c2 = c2g * 8 + j;
        float4 o4;
        o4.x = lo32(a[0][j]);
        o4.y = hi32(a[0][j]);
        o4.z = lo32(a[1][j]);
        o4.w = hi32(a[1][j]);
        *(float4*)(ob + c2 * SPATIAL) = o4;
    }
}

// ---------------------------------------------------------------------------
extern "C" void kernel_launch(void* const* d_in, const int* in_sizes, int n_in,
                              void* d_out, int out_size) {
    const float* q = (const float*)d_in[0];
    const float* k = (const float*)d_in[1];
    const float* v = (const float*)d_in[2];
    float* out = (float*)d_out;

    cudaFuncSetAttribute(phase1, cudaFuncAttributeMaxDynamicSharedMemorySize, P1_SMEM);

    phase1<<<dim3(NBW, 2), 256, P1_SMEM>>>(k, v);
    phase2<<<dim3(NBW, 7), 224>>>(q, out);
}

// round 8
// speedup vs baseline: 1.3257x; 1.3257x over previous
#include <cuda_runtime.h>

#define SPATIAL  3136
#define NBW      128
#define SCALE2   0.35355339059327373f   // 2/sqrt(32)

// ---- phase1 (R5): 4-row chunks, ring-3, two 7-chunk slices ----
#define P1_ROWB   512
#define P1_TEN    (32 * P1_ROWB)
#define P1_BUF    (2 * P1_TEN)
#define P1_SMEM   (3 * P1_BUF)          // 98304
#define P1_LPT    896

// ---- phase2: persistent, ring-3 of 8-row Q chunks ----
#define Q_CHUNK   28672                 // 32ch * 56 lines * 16B
#define P2_PSD    (3 * Q_CHUNK)         // psd offset
#define P2_SMEM   (P2_PSD + 4096)       // 90112

__device__ float g_Pp[NBW * 2 * 1024];

typedef unsigned long long ull;

__device__ __forceinline__ void fma2(ull& d, ull a, ull b) {
    asm("fma.rn.f32x2 %0, %1, %2, %0;" : "+l"(d) : "l"(a), "l"(b));
}
__device__ __forceinline__ ull rep2(float x) {
    ull r; asm("mov.b64 %0, {%1, %1};" : "=l"(r) : "f"(x)); return r;
}
__device__ __forceinline__ float lo32(ull x) { return __uint_as_float((unsigned)x); }
__device__ __forceinline__ float hi32(ull x) { return __uint_as_float((unsigned)(x >> 32)); }
__device__ __forceinline__ void cp16(unsigned dst, const void* src) {
    asm volatile("cp.async.cg.shared.global [%0], [%1], 16;" :: "r"(dst), "l"(src));
}

// ---------------------------------------------------------------------------
// Phase 1 (R5 verbatim): partial P = K^T V. grid (128,2), 256 thr, 2 blk/SM.
// ---------------------------------------------------------------------------
__global__ __launch_bounds__(256, 2)
void phase1(const float* __restrict__ K, const float* __restrict__ V) {
    extern __shared__ __align__(16) char sm[];
    const unsigned sm32 = (unsigned)__cvta_generic_to_shared(sm);

    const int tid  = threadIdx.x;
    const int bw   = blockIdx.x;
    const int sl   = blockIdx.y;
    const int c0   = sl * 7;

    const int win  = bw & 1;
    const int head = (bw >> 1) & 7;
    const int tb   = bw >> 4;
    const int base = (tb * 256 + head * 32) * SPATIAL + win * 28;

    const int ti  = tid & 3;
    const int tj  = (tid >> 2) & 7;
    const int wid = tid >> 5;
    const int keyA = ti * 2;
    const int keyB = ti * 2 + 1;

    auto stage = [&](int ch, int buf) {
        const unsigned bufb = sm32 + buf * P1_BUF;
        const int gofs = base + ch * 224;
        #pragma unroll
        for (int it = 0; it < 7; it++) {
            int idx = it * 256 + tid;
            int tensor = (idx >= P1_LPT) ? 1 : 0;
            int rem = idx - tensor * P1_LPT;
            int c = rem / 28;
            int g = rem - c * 28;
            int r = g / 7;
            int w4 = g - r * 7;
            const float* src = (tensor ? V : K) + gofs + c * SPATIAL + r * 56 + w4 * 4;
            int chs = g ^ ((c >> 2) & 7);
            cp16(bufb + tensor * P1_TEN + c * P1_ROWB + chs * 16, src);
        }
        asm volatile("cp.async.commit_group;");
    };

    ull acc[8][4];
    #pragma unroll
    for (int i = 0; i < 8; i++)
        #pragma unroll
        for (int j = 0; j < 4; j++) acc[i][j] = 0ull;

    stage(c0, 0);
    stage(c0 + 1, 1);

    #pragma unroll
    for (int i = 0; i < 7; i++) {
        if (i < 5) {
            stage(c0 + i + 2, (i + 2) % 3);
            asm volatile("cp.async.wait_group 2;");
        } else if (i == 5) {
            asm volatile("cp.async.wait_group 1;");
        } else {
            asm volatile("cp.async.wait_group 0;");
        }
        __syncthreads();

        const char* kB = sm + (i % 3) * P1_BUF;
        const char* vB = kB + P1_TEN;

        auto loadA = [&](int u, ull* ka) {
            const int pr = wid + u * 8;
            const int col = pr >> 1;
            const unsigned off = ((unsigned)(col ^ keyA) << 4) + ((pr & 1) << 3);
            #pragma unroll
            for (int i2 = 0; i2 < 4; i2++)
                ka[i2] = *(const ull*)(kB + (ti * 8 + i2) * P1_ROWB + off);
        };
        auto loadB = [&](int u, ull* kb) {
            const int pr = wid + u * 8;
            const int col = pr >> 1;
            const unsigned off = ((unsigned)(col ^ keyB) << 4) + ((pr & 1) << 3);
            #pragma unroll
            for (int i2 = 0; i2 < 4; i2++)
                kb[i2] = *(const ull*)(kB + (ti * 8 + 4 + i2) * P1_ROWB + off);
        };
        auto loadV = [&](int u, ull* v) {
            const int pr = wid + u * 8;
            const int col = pr >> 1;
            const unsigned off = ((unsigned)(col ^ tj) << 4) + ((pr & 1) << 3);
            #pragma unroll
            for (int j = 0; j < 4; j++)
                v[j] = *(const ull*)(vB + (tj * 4 + j) * P1_ROWB + off);
        };

        ull kkA[4], kkB[4], vv[4], kkA2[4], vv2[4];
        loadA(0, kkA);
        loadV(0, vv);
        #pragma unroll
        for (int u = 0; u < 7; u++) {
            loadB(u, kkB);
            if (u < 6) { loadA(u + 1, kkA2); loadV(u + 1, vv2); }
            #pragma unroll
            for (int i2 = 0; i2 < 4; i2++)
                #pragma unroll
                for (int j = 0; j < 4; j++)
                    fma2(acc[i2][j], kkA[i2], vv[j]);
            #pragma unroll
            for (int i2 = 0; i2 < 4; i2++)
                #pragma unroll
                for (int j = 0; j < 4; j++)
                    fma2(acc[4 + i2][j], kkB[i2], vv[j]);
            if (u < 6) {
                #pragma unroll
                for (int t = 0; t < 4; t++) { kkA[t] = kkA2[t]; vv[t] = vv2[t]; }
            }
        }
        __syncthreads();
    }

    float* red = (float*)sm;
    #pragma unroll
    for (int i2 = 0; i2 < 8; i2++)
        #pragma unroll
        for (int j = 0; j < 4; j++)
            red[wid * 1024 + (ti * 8 + i2) * 32 + tj * 4 + j] =
                lo32(acc[i2][j]) + hi32(acc[i2][j]);
    __syncthreads();

    float* gp = g_Pp + (bw * 2 + sl) * 1024;
    #pragma unroll
    for (int t = 0; t < 4; t++) {
        const int o = tid + t * 256;
        float s = red[o];
        #pragma unroll
        for (int w = 1; w < 8; w++) s += red[w * 1024 + o];
        gp[o] = s;
    }
}

// ---------------------------------------------------------------------------
// Phase 2 (persistent): out = Q * P. grid (128 bw, 2 slices of 28 rows),
// 256 threads, ring-3 staging of 8-row chunks {8,8,8,4}. Tile 8pos x 4c2.
// ---------------------------------------------------------------------------
__global__ __launch_bounds__(256, 2)
void phase2(const float* __restrict__ Q, float* __restrict__ O) {
    extern __shared__ __align__(16) char sm[];
    const unsigned sm32 = (unsigned)__cvta_generic_to_shared(sm);
    float* psd = (float*)(sm + P2_PSD);

    const int tid = threadIdx.x;
    const int bw  = blockIdx.x;
    const int sl  = blockIdx.y;
    const int win  = bw & 1;
    const int head = (bw >> 1) & 7;
    const int tb   = bw >> 4;
    const int base = (tb * 256 + head * 32) * SPATIAL + win * 28 + sl * 1568;

    // stage: chunk ch (rows ch*8..), nlines lines per channel (56 or 28)
    auto stage = [&](int ch, int buf, int nlines) {
        const unsigned bufb = sm32 + buf * Q_CHUNK;
        const int gofs = base + ch * 448;
        const int tot = 32 * nlines;
        #pragma unroll
        for (int it = 0; it < 7; it++) {
            int idx = it * 256 + tid;
            if (idx < tot) {
                int c = idx / nlines;
                int g = idx - c * nlines;
                int r = g / 7;
                int w4 = g - r * 7;
                cp16(bufb + (c * 56 + g) * 16,
                     Q + gofs + c * SPATIAL + r * 56 + w4 * 4);
            }
        }
        asm volatile("cp.async.commit_group;");
    };

    stage(0, 0, 56);
    stage(1, 1, 56);
    stage(2, 2, 56);

    // P = (partial0 + partial1) * scale  (1024 floats, one float4/thread)
    {
        const float* p0 = g_Pp + bw * 2048;
        const int i4 = tid * 4;
        float4 a = *(const float4*)(p0 + i4);
        float4 b = *(const float4*)(p0 + 1024 + i4);
        float4 s;
        s.x = (a.x + b.x) * SCALE2;
        s.y = (a.y + b.y) * SCALE2;
        s.z = (a.z + b.z) * SCALE2;
        s.w = (a.w + b.w) * SCALE2;
        *(float4*)&psd[i4] = s;
    }

    const int c2g  = tid & 7;           // 4 c2 each
    const int posg = tid >> 3;           // 0..31
    const int pbase = posg * 8;

    auto compute = [&](int ch, int buf, int npos) {
        const char* qB = sm + buf * Q_CHUNK;
        if (pbase < npos) {
            ull a[4][4];
            #pragma unroll
            for (int p = 0; p < 4; p++)
                #pragma unroll
                for (int j = 0; j < 4; j++) a[p][j] = 0ull;

            #pragma unroll
            for (int c1 = 0; c1 < 32; c1++) {
                ulonglong2 qa = *(const ulonglong2*)(qB + (c1 * 56 + posg * 2) * 16);
                ulonglong2 qb = *(const ulonglong2*)(qB + (c1 * 56 + posg * 2) * 16 + 16);
                float4 pv = *(const float4*)&psd[c1 * 32 + c2g * 4];
                ull pj;
                pj = rep2(pv.x);
                fma2(a[0][0], qa.x, pj); fma2(a[1][0], qa.y, pj);
                fma2(a[2][0], qb.x, pj); fma2(a[3][0], qb.y, pj);
                pj = rep2(pv.y);
                fma2(a[0][1], qa.x, pj); fma2(a[1][1], qa.y, pj);
                fma2(a[2][1], qb.x, pj); fma2(a[3][1], qb.y, pj);
                pj = rep2(pv.z);
                fma2(a[0][2], qa.x, pj); fma2(a[1][2], qa.y, pj);
                fma2(a[2][2], qb.x, pj); fma2(a[3][2], qb.y, pj);
                pj = rep2(pv.w);
                fma2(a[0][3], qa.x, pj); fma2(a[1][3], qa.y, pj);
                fma2(a[2][3], qb.x, pj); fma2(a[3][3], qb.y, pj);
            }

            const int obase = base + ch * 448;
            #pragma unroll
            for (int j = 0; j < 4; j++) {
                const int c2 = c2g * 4 + j;
                #pragma unroll
                for (int h = 0; h < 2; h++) {
                    const int p  = pbase + h * 4;
                    const int rr = p / 28;
                    const int ww = p - rr * 28;
                    float4 o4;
                    o4.x = lo32(a[2 * h][j]);
                    o4.y = hi32(a[2 * h][j]);
                    o4.z = lo32(a[2 * h + 1][j]);
                    o4.w = hi32(a[2 * h + 1][j]);
                    *(float4*)(O + obase + c2 * SPATIAL + rr * 56 + ww) = o4;
                }
            }
        }
    };

    // ch0
    asm volatile("cp.async.wait_group 2;");
    __syncthreads();
    compute(0, 0, 224);
    __syncthreads();                       // buf0 free before restage
    stage(3, 0, 28);
    // ch1
    asm volatile("cp.async.wait_group 2;");
    __syncthreads();
    compute(1, 1, 224);
    // ch2
    asm volatile("cp.async.wait_group 1;");
    __syncthreads();
    compute(2, 2, 224);
    // ch3 (4 rows)
    asm volatile("cp.async.wait_group 0;");
    __syncthreads();
    compute(3, 0, 112);
}

// ---------------------------------------------------------------------------
extern "C" void kernel_launch(void* const* d_in, const int* in_sizes, int n_in,
                              void* d_out, int out_size) {
    const float* q = (const float*)d_in[0];
    const float* k = (const float*)d_in[1];
    const float* v = (const float*)d_in[2];
    float* out = (float*)d_out;

    cudaFuncSetAttribute(phase1, cudaFuncAttributeMaxDynamicSharedMemorySize, P1_SMEM);
    cudaFuncSetAttribute(phase2, cudaFuncAttributeMaxDynamicSharedMemorySize, P2_SMEM);

    phase1<<<dim3(NBW, 2), 256, P1_SMEM>>>(k, v);
    phase2<<<dim3(NBW, 2), 256, P2_SMEM>>>(q, out);
}

// round 9
// speedup vs baseline: 1.4803x; 1.1166x over previous
#include <cuda_runtime.h>

#define SPATIAL  3136
#define NBW      128
#define SCALE2   0.35355339059327373f   // 2/sqrt(32)

// smem: K[0,28672) V[28672,57344) for phase1; Q[0,28672) + psd[28672,32768) for phase2
#define ROWB     896                    // 56 lines * 16B per channel
#define TEN      28672
#define SMEM_TOT 57344

__device__ float g_Pp[NBW * 7 * 1024];   // partial K^T V per (bw, chunk)
__device__ int   g_ready[NBW];           // sticky per-bw producer count

typedef unsigned long long ull;

__device__ __forceinline__ void fma2(ull& d, ull a, ull b) {
    asm("fma.rn.f32x2 %0, %1, %2, %0;" : "+l"(d) : "l"(a), "l"(b));
}
__device__ __forceinline__ float lo32(ull x) { return __uint_as_float((unsigned)x); }
__device__ __forceinline__ float hi32(ull x) { return __uint_as_float((unsigned)(x >> 32)); }
__device__ __forceinline__ void cp16(unsigned dst, const void* src) {
    asm volatile("cp.async.cg.shared.global [%0], [%1], 16;" :: "r"(dst), "l"(src));
}

__global__ __launch_bounds__(128, 4)
void fused(const float* __restrict__ K, const float* __restrict__ V,
           const float* __restrict__ Q, float* __restrict__ O) {
    extern __shared__ __align__(16) char sm[];
    const unsigned sm32 = (unsigned)__cvta_generic_to_shared(sm);

    const int tid = threadIdx.x;
    const int bj  = blockIdx.x;          // 0..895
    const int bw  = bj / 7;
    const int j   = bj - bw * 7;         // chunk 0..6 (8 rows each)

    const int win  = bw & 1;
    const int head = (bw >> 1) & 7;
    const int tb   = bw >> 4;
    const int base = (tb * 256 + head * 32) * SPATIAL + win * 28;
    const int gch  = base + j * 448;     // this block's 8-row chunk

    // ================= PHASE 1 part: partial P = K_chunk^T V_chunk ========
    // stage half h (lines 28h..28h+27 of both tensors), 14 cp.async/thread
    auto stageKV = [&](int h) {
        #pragma unroll
        for (int it = 0; it < 14; it++) {
            int idx = it * 128 + tid;            // 0..1791
            int tensor = (idx >= 896) ? 1 : 0;
            int rem = idx - tensor * 896;        // 0..895 = 32ch * 28 lines
            int c = rem / 28;
            int g = rem - c * 28 + h * 28;       // line 0..55
            int r = g / 7;
            int w4 = g - r * 7;
            const float* src = (tensor ? V : K) + gch + c * SPATIAL + r * 56 + w4 * 4;
            int chs = g ^ ((c >> 2) & 7);
            cp16(sm32 + tensor * TEN + c * ROWB + chs * 16, src);
        }
        asm volatile("cp.async.commit_group;");
    };
    stageKV(0);
    stageKV(1);

    const int ti  = tid & 3;             // 8 c1 channels
    const int tj  = (tid >> 2) & 7;      // 4 c2 channels
    const int wid = tid >> 5;            // line-group (4 warps)
    const int keyA = ti * 2;
    const int keyB = ti * 2 + 1;

    ull acc[8][4];
    #pragma unroll
    for (int i = 0; i < 8; i++)
        #pragma unroll
        for (int jj = 0; jj < 4; jj++) acc[i][jj] = 0ull;

    const char* kB = sm;
    const char* vB = sm + TEN;

    asm volatile("cp.async.wait_group 1;");
    __syncthreads();

    #pragma unroll
    for (int half = 0; half < 2; half++) {
        if (half == 1) {
            asm volatile("cp.async.wait_group 0;");
            __syncthreads();
        }
        #pragma unroll
        for (int u = 0; u < 7; u++) {
            const int line = wid + u * 4 + half * 28;   // 0..55
            ulonglong2 vv[4];
            #pragma unroll
            for (int j2 = 0; j2 < 4; j2++)
                vv[j2] = *(const ulonglong2*)(vB + (tj * 4 + j2) * ROWB
                          + ((line ^ tj) << 4));
            {
                ulonglong2 kk[4];
                #pragma unroll
                for (int i2 = 0; i2 < 4; i2++)
                    kk[i2] = *(const ulonglong2*)(kB + (ti * 8 + i2) * ROWB
                              + ((line ^ keyA) << 4));
                #pragma unroll
                for (int i2 = 0; i2 < 4; i2++)
                    #pragma unroll
                    for (int j2 = 0; j2 < 4; j2++) {
                        fma2(acc[i2][j2], kk[i2].x, vv[j2].x);
                        fma2(acc[i2][j2], kk[i2].y, vv[j2].y);
                    }
            }
            {
                ulonglong2 kk[4];
                #pragma unroll
                for (int i2 = 0; i2 < 4; i2++)
                    kk[i2] = *(const ulonglong2*)(kB + (ti * 8 + 4 + i2) * ROWB
                              + ((line ^ keyB) << 4));
                #pragma unroll
                for (int i2 = 0; i2 < 4; i2++)
                    #pragma unroll
                    for (int j2 = 0; j2 < 4; j2++) {
                        fma2(acc[4 + i2][j2], kk[i2].x, vv[j2].x);
                        fma2(acc[4 + i2][j2], kk[i2].y, vv[j2].y);
                    }
            }
        }
    }
    __syncthreads();                      // done reading K/V; reuse smem

    // reduce 4 line-warps -> partial P in global
    float* red = (float*)sm;              // 4 * 1024 floats = 16KB
    #pragma unroll
    for (int i2 = 0; i2 < 8; i2++)
        #pragma unroll
        for (int j2 = 0; j2 < 4; j2++)
            red[wid * 1024 + (ti * 8 + i2) * 32 + tj * 4 + j2] =
                lo32(acc[i2][j2]) + hi32(acc[i2][j2]);
    __syncthreads();

    float* gp = g_Pp + bj * 1024;
    #pragma unroll
    for (int t = 0; t < 8; t++) {
        const int o = tid + t * 128;
        gp[o] = red[o] + red[1024 + o] + red[2048 + o] + red[3072 + o];
    }
    __threadfence();
    if (tid == 0) atomicAdd(&g_ready[bw], 1);
    __syncthreads();                      // red reads done; reuse smem for Q

    // ================= PHASE 2 part: out_chunk = Q_chunk * P ===============
    // stage Q chunk j with line swizzle g^( (g>>3)&7 )  (overlaps the spin)
    #pragma unroll
    for (int it = 0; it < 14; it++) {
        int idx = it * 128 + tid;             // 0..1791
        int c = idx / 56;
        int g = idx - c * 56;                 // line 0..55
        int r = g / 7;
        int w4 = g - r * 7;
        int sl = g ^ ((g >> 3) & 7);
        cp16(sm32 + (c * 56 + sl) * 16,
             Q + gch + c * SPATIAL + r * 56 + w4 * 4);
    }
    asm volatile("cp.async.commit_group;");

    // wait for all 7 producers of this bw (sticky across graph replays)
    if (tid == 0) {
        while (((volatile int*)g_ready)[bw] < 7) { }
    }
    __syncthreads();
    __threadfence();

    // psd = scale * sum of 7 partials (L2-hot)
    float* psd = (float*)(sm + TEN);
    {
        const float* pp = g_Pp + bw * 7168;
        const int i8 = tid * 8;
        float4 sa = make_float4(0.f, 0.f, 0.f, 0.f);
        float4 sb = sa;
        #pragma unroll
        for (int c = 0; c < 7; c++) {
            float4 la = *(const float4*)(pp + c * 1024 + i8);
            float4 lb = *(const float4*)(pp + c * 1024 + i8 + 4);
            sa.x += la.x; sa.y += la.y; sa.z += la.z; sa.w += la.w;
            sb.x += lb.x; sb.y += lb.y; sb.z += lb.z; sb.w += lb.w;
        }
        sa.x *= SCALE2; sa.y *= SCALE2; sa.z *= SCALE2; sa.w *= SCALE2;
        sb.x *= SCALE2; sb.y *= SCALE2; sb.z *= SCALE2; sb.w *= SCALE2;
        *(float4*)&psd[i8] = sa;
        *(float4*)&psd[i8 + 4] = sb;
    }

    asm volatile("cp.async.wait_group 0;");
    __syncthreads();

    const int c2g  = tid & 3;             // 8 c2 each
    const int posg = tid >> 2;             // 0..31, active < 28
    if (posg >= 28) return;
    const int la = posg * 2;               // qa line
    const int lb = posg * 2 + 1;            // qb line
    const unsigned offa = (unsigned)(la ^ ((la >> 3) & 7)) << 4;
    const unsigned offb = (unsigned)(lb ^ ((lb >> 3) & 7)) << 4;
    const int pbase = posg * 8;

    ull a[4][8];
    #pragma unroll
    for (int p = 0; p < 4; p++)
        #pragma unroll
        for (int j2 = 0; j2 < 8; j2++) a[p][j2] = 0ull;

    ulonglong2 qa = *(const ulonglong2*)(sm + offa);
    ulonglong2 qb = *(const ulonglong2*)(sm + offb);
    float4 pa = *(const float4*)&psd[c2g * 8];
    float4 pb = *(const float4*)&psd[c2g * 8 + 4];

    #pragma unroll
    for (int c1 = 0; c1 < 32; c1++) {
        ulonglong2 qa2, qb2;
        float4 pa2, pb2;
        if (c1 < 31) {
            qa2 = *(const ulonglong2*)(sm + (c1 + 1) * ROWB + offa);
            qb2 = *(const ulonglong2*)(sm + (c1 + 1) * ROWB + offb);
            pa2 = *(const float4*)&psd[(c1 + 1) * 32 + c2g * 8];
            pb2 = *(const float4*)&psd[(c1 + 1) * 32 + c2g * 8 + 4];
        }
        const float pv[8] = {pa.x, pa.y, pa.z, pa.w, pb.x, pb.y, pb.z, pb.w};
        #pragma unroll
        for (int j2 = 0; j2 < 8; j2++) {
            ull pj;
            asm("mov.b64 %0, {%1, %1};" : "=l"(pj) : "f"(pv[j2]));
            fma2(a[0][j2], qa.x, pj);
            fma2(a[1][j2], qa.y, pj);
            fma2(a[2][j2], qb.x, pj);
            fma2(a[3][j2], qb.y, pj);
        }
        if (c1 < 31) { qa = qa2; qb = qb2; pa = pa2; pb = pb2; }
    }

    #pragma unroll
    for (int j2 = 0; j2 < 8; j2++) {
        const int c2 = c2g * 8 + j2;
        #pragma unroll
        for (int h = 0; h < 2; h++) {
            const int p  = pbase + h * 4;
            const int rr = p / 28;
            const int ww = p - rr * 28;
            float4 o4;
            o4.x = lo32(a[2 * h][j2]);
            o4.y = hi32(a[2 * h][j2]);
            o4.z = lo32(a[2 * h + 1][j2]);
            o4.w = hi32(a[2 * h + 1][j2]);
            *(float4*)(O + gch + c2 * SPATIAL + rr * 56 + ww) = o4;
        }
    }
}

// ---------------------------------------------------------------------------
extern "C" void kernel_launch(void* const* d_in, const int* in_sizes, int n_in,
                              void* d_out, int out_size) {
    const float* q = (const float*)d_in[0];
    const float* k = (const float*)d_in[1];
    const float* v = (const float*)d_in[2];
    float* out = (float*)d_out;

    cudaFuncSetAttribute(fused, cudaFuncAttributeMaxDynamicSharedMemorySize, SMEM_TOT);
    fused<<<NBW * 7, 128, SMEM_TOT>>>(k, v, q, out);
}

// round 10
// speedup vs baseline: 1.5437x; 1.0428x over previous
#include <cuda_runtime.h>

#define SPATIAL  3136
#define NBW      128
#define SCALE2   0.35355339059327373f   // 2/sqrt(32)

// phase1: 4-row chunks = 112 positions = 56 pairs, 28 16B-lines per channel
#define P1_ROWB   512
#define P1_TEN    (32 * P1_ROWB)
#define P1_BUF    (2 * P1_TEN)
#define P1_SMEM   (3 * P1_BUF)          // 98304
#define P1_LPT    896

__device__ float g_Pp[NBW * 2 * 1024];

typedef unsigned long long ull;

__device__ __forceinline__ void fma2(ull& d, ull a, ull b) {
    asm("fma.rn.f32x2 %0, %1, %2, %0;" : "+l"(d) : "l"(a), "l"(b));
}
__device__ __forceinline__ ull rep2(float x) {
    ull r; asm("mov.b64 %0, {%1, %1};" : "=l"(r) : "f"(x)); return r;
}
__device__ __forceinline__ float lo32(ull x) { return __uint_as_float((unsigned)x); }
__device__ __forceinline__ float hi32(ull x) { return __uint_as_float((unsigned)(x >> 32)); }
__device__ __forceinline__ void cp16(unsigned dst, const void* src) {
    asm volatile("cp.async.cg.shared.global [%0], [%1], 16;" :: "r"(dst), "l"(src));
}

// ---------------------------------------------------------------------------
// Phase 1 (R5 verbatim): partial P = K^T V. grid (128,2), 256 thr, 2 blk/SM.
// ---------------------------------------------------------------------------
__global__ __launch_bounds__(256, 2)
void phase1(const float* __restrict__ K, const float* __restrict__ V) {
    extern __shared__ __align__(16) char sm[];
    const unsigned sm32 = (unsigned)__cvta_generic_to_shared(sm);

    const int tid  = threadIdx.x;
    const int bw   = blockIdx.x;
    const int sl   = blockIdx.y;
    const int c0   = sl * 7;

    const int win  = bw & 1;
    const int head = (bw >> 1) & 7;
    const int tb   = bw >> 4;
    const int base = (tb * 256 + head * 32) * SPATIAL + win * 28;

    const int ti  = tid & 3;
    const int tj  = (tid >> 2) & 7;
    const int wid = tid >> 5;
    const int keyA = ti * 2;
    const int keyB = ti * 2 + 1;

    auto stage = [&](int ch, int buf) {
        const unsigned bufb = sm32 + buf * P1_BUF;
        const int gofs = base + ch * 224;
        #pragma unroll
        for (int it = 0; it < 7; it++) {
            int idx = it * 256 + tid;
            int tensor = (idx >= P1_LPT) ? 1 : 0;
            int rem = idx - tensor * P1_LPT;
            int c = rem / 28;
            int g = rem - c * 28;
            int r = g / 7;
            int w4 = g - r * 7;
            const float* src = (tensor ? V : K) + gofs + c * SPATIAL + r * 56 + w4 * 4;
            int chs = g ^ ((c >> 2) & 7);
            cp16(bufb + tensor * P1_TEN + c * P1_ROWB + chs * 16, src);
        }
        asm volatile("cp.async.commit_group;");
    };

    ull acc[8][4];
    #pragma unroll
    for (int i = 0; i < 8; i++)
        #pragma unroll
        for (int j = 0; j < 4; j++) acc[i][j] = 0ull;

    stage(c0, 0);
    stage(c0 + 1, 1);

    #pragma unroll
    for (int i = 0; i < 7; i++) {
        if (i < 5) {
            stage(c0 + i + 2, (i + 2) % 3);
            asm volatile("cp.async.wait_group 2;");
        } else if (i == 5) {
            asm volatile("cp.async.wait_group 1;");
        } else {
            asm volatile("cp.async.wait_group 0;");
        }
        __syncthreads();

        const char* kB = sm + (i % 3) * P1_BUF;
        const char* vB = kB + P1_TEN;

        auto loadA = [&](int u, ull* ka) {
            const int pr = wid + u * 8;
            const int col = pr >> 1;
            const unsigned off = ((unsigned)(col ^ keyA) << 4) + ((pr & 1) << 3);
            #pragma unroll
            for (int i2 = 0; i2 < 4; i2++)
                ka[i2] = *(const ull*)(kB + (ti * 8 + i2) * P1_ROWB + off);
        };
        auto loadB = [&](int u, ull* kb) {
            const int pr = wid + u * 8;
            const int col = pr >> 1;
            const unsigned off = ((unsigned)(col ^ keyB) << 4) + ((pr & 1) << 3);
            #pragma unroll
            for (int i2 = 0; i2 < 4; i2++)
                kb[i2] = *(const ull*)(kB + (ti * 8 + 4 + i2) * P1_ROWB + off);
        };
        auto loadV = [&](int u, ull* v) {
            const int pr = wid + u * 8;
            const int col = pr >> 1;
            const unsigned off = ((unsigned)(col ^ tj) << 4) + ((pr & 1) << 3);
            #pragma unroll
            for (int j = 0; j < 4; j++)
                v[j] = *(const ull*)(vB + (tj * 4 + j) * P1_ROWB + off);
        };

        ull kkA[4], kkB[4], vv[4], kkA2[4], vv2[4];
        loadA(0, kkA);
        loadV(0, vv);
        #pragma unroll
        for (int u = 0; u < 7; u++) {
            loadB(u, kkB);
            if (u < 6) { loadA(u + 1, kkA2); loadV(u + 1, vv2); }
            #pragma unroll
            for (int i2 = 0; i2 < 4; i2++)
                #pragma unroll
                for (int j = 0; j < 4; j++)
                    fma2(acc[i2][j], kkA[i2], vv[j]);
            #pragma unroll
            for (int i2 = 0; i2 < 4; i2++)
                #pragma unroll
                for (int j = 0; j < 4; j++)
                    fma2(acc[4 + i2][j], kkB[i2], vv[j]);
            if (u < 6) {
                #pragma unroll
                for (int t = 0; t < 4; t++) { kkA[t] = kkA2[t]; vv[t] = vv2[t]; }
            }
        }
        __syncthreads();
    }

    float* red = (float*)sm;
    #pragma unroll
    for (int i2 = 0; i2 < 8; i2++)
        #pragma unroll
        for (int j = 0; j < 4; j++)
            red[wid * 1024 + (ti * 8 + i2) * 32 + tj * 4 + j] =
                lo32(acc[i2][j]) + hi32(acc[i2][j]);
    __syncthreads();

    float* gp = g_Pp + (bw * 2 + sl) * 1024;
    #pragma unroll
    for (int t = 0; t < 4; t++) {
        const int o = tid + t * 256;
        float s = red[o];
        #pragma unroll
        for (int w = 1; w < 8; w++) s += red[w * 1024 + o];
        gp[o] = s;
    }
}

// ---------------------------------------------------------------------------
// Phase 2: out = Q * P. grid (128 bw, 7 chunks of 8 rows), 128 threads.
// R5 tile (8pos x 8c2, balanced crossbar ratio), NO software prefetch,
// launch_bounds(128,5) -> 5 blocks/SM (20 warps): TLP hides LDS latency.
// ---------------------------------------------------------------------------
__global__ __launch_bounds__(128, 5)
void phase2(const float* __restrict__ Q, float* __restrict__ O) {
    __shared__ __align__(16) float qs[32 * 224];
    __shared__ __align__(16) float ps[1024];

    const int tid = threadIdx.x;
    const int bw  = blockIdx.x;
    const int ck  = blockIdx.y;
    const int win  = bw & 1;
    const int head = (bw >> 1) & 7;
    const int tb   = bw >> 4;
    const int base = (tb * 256 + head * 32) * SPATIAL + win * 28 + ck * 448;

    // stage Q tile via cp.async: 1792 lines / 128 thr = 14 each
    const unsigned qsa = (unsigned)__cvta_generic_to_shared(qs);
    #pragma unroll
    for (int it = 0; it < 14; it++) {
        int idx = it * 128 + tid;
        int c = idx / 56;
        int g = idx - c * 56;
        int r = g / 7;
        int w4 = g - r * 7;
        cp16(qsa + (c * 224 + g * 4) * 4,
             Q + base + c * SPATIAL + r * 56 + w4 * 4);
    }
    asm volatile("cp.async.commit_group;");

    // P = (partial0 + partial1) * scale while Q streams
    {
        const float* p0 = g_Pp + bw * 2048;
        #pragma unroll
        for (int t = 0; t < 2; t++) {
            const int i4 = (tid + t * 128) * 4;
            float4 a = *(const float4*)(p0 + i4);
            float4 b = *(const float4*)(p0 + 1024 + i4);
            float4 s;
            s.x = (a.x + b.x) * SCALE2;
            s.y = (a.y + b.y) * SCALE2;
            s.z = (a.z + b.z) * SCALE2;
            s.w = (a.w + b.w) * SCALE2;
            *(float4*)&ps[i4] = s;
        }
    }

    asm volatile("cp.async.wait_group 0;");
    __syncthreads();

    const int c2g  = tid & 3;            // 8 c2 each
    const int posg = tid >> 2;            // 0..31, active < 28
    if (posg >= 28) return;
    const int pbase = posg * 8;

    ull a[4][8];
    #pragma unroll
    for (int p = 0; p < 4; p++)
        #pragma unroll
        for (int j = 0; j < 8; j++) a[p][j] = 0ull;

    #pragma unroll
    for (int c1 = 0; c1 < 32; c1++) {
        ulonglong2 qa = *(const ulonglong2*)&qs[c1 * 224 + pbase];
        ulonglong2 qb = *(const ulonglong2*)&qs[c1 * 224 + pbase + 4];
        float4 pa = *(const float4*)&ps[c1 * 32 + c2g * 8];
        float4 pb = *(const float4*)&ps[c1 * 32 + c2g * 8 + 4];
        const float pv[8] = {pa.x, pa.y, pa.z, pa.w, pb.x, pb.y, pb.z, pb.w};
        #pragma unroll
        for (int j = 0; j < 8; j++) {
            ull pj = rep2(pv[j]);
            fma2(a[0][j], qa.x, pj);
            fma2(a[1][j], qa.y, pj);
            fma2(a[2][j], qb.x, pj);
            fma2(a[3][j], qb.y, pj);
        }
    }

    #pragma unroll
    for (int j = 0; j < 8; j++) {
        const int c2 = c2g * 8 + j;
        #pragma unroll
        for (int h = 0; h < 2; h++) {
            const int p  = pbase + h * 4;
            const int rr = p / 28;
            const int ww = p - rr * 28;
            float4 o4;
            o4.x = lo32(a[2 * h][j]);
            o4.y = hi32(a[2 * h][j]);
            o4.z = lo32(a[2 * h + 1][j]);
            o4.w = hi32(a[2 * h + 1][j]);
            *(float4*)(O + base + c2 * SPATIAL + rr * 56 + ww) = o4;
        }
    }
}

// ---------------------------------------------------------------------------
extern "C" void kernel_launch(void* const* d_in, const int* in_sizes, int n_in,
                              void* d_out, int out_size) {
    const float* q = (const float*)d_in[0];
    const float* k = (const float*)d_in[1];
    const float* v = (const float*)d_in[2];
    float* out = (float*)d_out;

    cudaFuncSetAttribute(phase1, cudaFuncAttributeMaxDynamicSharedMemorySize, P1_SMEM);

    phase1<<<dim3(NBW, 2), 256, P1_SMEM>>>(k, v);
    phase2<<<dim3(NBW, 7), 128>>>(q, out);
}